// round 1
// baseline (speedup 1.0000x reference)
#include <cuda_runtime.h>
#include <math.h>

#define BB 2
#define LL 4096
#define DD 512
#define HH 8
#define DKK 64
#define MROWS (BB*LL)          // 8192
#define QKVN (3*DD)            // 1536
#define ATTN_SCALE 0.125f      // 1/sqrt(64)

// Scratch (allocation-free rule: __device__ globals)
__device__ float g_qkv[(size_t)MROWS * QKVN];   // [B*L, 3*D]
__device__ float g_ctx[(size_t)MROWS * DD];     // [B*L, D]

// ---------------------------------------------------------------------------
// GEMM: C[M,N] = A[M,K] @ W[N,K]^T   (row-major, lda=K, ldc=N)
// 64x64 tiles, BK=16, 256 threads, 4x4 per-thread micro-tile.
// ---------------------------------------------------------------------------
__global__ __launch_bounds__(256) void gemm_nt_kernel(
    const float* __restrict__ A, const float* __restrict__ W,
    float* __restrict__ C, int M, int N, int K)
{
    __shared__ float As[16][68];   // [k][m], pad 4 -> 16B-aligned float4 rows
    __shared__ float Bs[16][68];   // [k][n]

    const int tid = threadIdx.x;
    const int tx = tid & 15;
    const int ty = tid >> 4;
    const int m0 = blockIdx.y * 64;
    const int n0 = blockIdx.x * 64;

    float acc[4][4] = {};

    const int lr = tid >> 2;          // 0..63 : tile row loaded by this thread
    const int lk = (tid & 3) * 4;     // 0,4,8,12 : k offset

    for (int k0 = 0; k0 < K; k0 += 16) {
        float4 va = *reinterpret_cast<const float4*>(&A[(size_t)(m0 + lr) * K + k0 + lk]);
        float4 vb = *reinterpret_cast<const float4*>(&W[(size_t)(n0 + lr) * K + k0 + lk]);
        As[lk + 0][lr] = va.x; As[lk + 1][lr] = va.y; As[lk + 2][lr] = va.z; As[lk + 3][lr] = va.w;
        Bs[lk + 0][lr] = vb.x; Bs[lk + 1][lr] = vb.y; Bs[lk + 2][lr] = vb.z; Bs[lk + 3][lr] = vb.w;
        __syncthreads();

#pragma unroll
        for (int k = 0; k < 16; k++) {
            float4 ra = *reinterpret_cast<const float4*>(&As[k][ty * 4]);
            float4 rb = *reinterpret_cast<const float4*>(&Bs[k][tx * 4]);
            float a4[4] = {ra.x, ra.y, ra.z, ra.w};
            float b4[4] = {rb.x, rb.y, rb.z, rb.w};
#pragma unroll
            for (int a = 0; a < 4; a++)
#pragma unroll
                for (int b = 0; b < 4; b++)
                    acc[a][b] = fmaf(a4[a], b4[b], acc[a][b]);
        }
        __syncthreads();
    }

#pragma unroll
    for (int a = 0; a < 4; a++) {
        float4 v = make_float4(acc[a][0], acc[a][1], acc[a][2], acc[a][3]);
        *reinterpret_cast<float4*>(&C[(size_t)(m0 + ty * 4 + a) * N + n0 + tx * 4]) = v;
    }
}

// ---------------------------------------------------------------------------
// Flash attention, fp32. One block = 64 query rows of one (b,h).
// Tiles: Br=Bc=64, DK=64. Online softmax, O accumulated in registers (4x4).
// qkv layout: [B*L, 1536], Q at col h*64, K at 512+h*64, V at 1024+h*64.
// ---------------------------------------------------------------------------
#define APAD 68
#define ASM_FLOATS (4 * 64 * APAD + 3 * 64)
#define ASM_BYTES  (ASM_FLOATS * 4)

__global__ __launch_bounds__(256) void attn_kernel(
    const float* __restrict__ qkv, float* __restrict__ ctx)
{
    extern __shared__ float sm[];
    float (*Qs)[APAD] = (float(*)[APAD])(sm);
    float (*Ks)[APAD] = (float(*)[APAD])(sm + 64 * APAD);
    float (*Vs)[APAD] = (float(*)[APAD])(sm + 2 * 64 * APAD);
    float (*Ps)[APAD] = (float(*)[APAD])(sm + 3 * 64 * APAD);
    float* row_m     = sm + 4 * 64 * APAD;
    float* row_l     = row_m + 64;
    float* row_alpha = row_l + 64;

    const int tid = threadIdx.x;
    const int tx = tid & 15;
    const int ty = tid >> 4;
    const int bh = blockIdx.y;            // 0..B*H-1
    const int b  = bh / HH;
    const int h  = bh % HH;
    const int q0 = blockIdx.x * 64;

    const float* base = qkv + (size_t)b * LL * QKVN + h * DKK;

    // Load Q tile (64x64)
    {
        const int r = tid >> 2;
        const int c = (tid & 3) * 16;
        const float* qrow = base + (size_t)(q0 + r) * QKVN;
#pragma unroll
        for (int j = 0; j < 16; j += 4) {
            float4 v = *reinterpret_cast<const float4*>(qrow + c + j);
            *reinterpret_cast<float4*>(&Qs[r][c + j]) = v;
        }
    }
    if (tid < 64) { row_m[tid] = -1e30f; row_l[tid] = 0.0f; }

    float o[4][4] = {};
    __syncthreads();

    for (int kt = 0; kt < LL; kt += 64) {
        // Load K and V tiles
        {
            const int r = tid >> 2;
            const int c = (tid & 3) * 16;
            const float* krow = base + (size_t)(kt + r) * QKVN + DD;
            const float* vrow = krow + DD;
#pragma unroll
            for (int j = 0; j < 16; j += 4) {
                float4 vk = *reinterpret_cast<const float4*>(krow + c + j);
                *reinterpret_cast<float4*>(&Ks[r][c + j]) = vk;
                float4 vv = *reinterpret_cast<const float4*>(vrow + c + j);
                *reinterpret_cast<float4*>(&Vs[r][c + j]) = vv;
            }
        }
        __syncthreads();

        // S = Q @ K^T  (4x4 per thread)
        float s[4][4] = {};
#pragma unroll
        for (int d = 0; d < 64; d++) {
            float rq[4], rk[4];
#pragma unroll
            for (int a = 0; a < 4; a++) rq[a] = Qs[ty * 4 + a][d];
#pragma unroll
            for (int bb = 0; bb < 4; bb++) rk[bb] = Ks[tx * 4 + bb][d];
#pragma unroll
            for (int a = 0; a < 4; a++)
#pragma unroll
                for (int bb = 0; bb < 4; bb++)
                    s[a][bb] = fmaf(rq[a], rk[bb], s[a][bb]);
        }
#pragma unroll
        for (int a = 0; a < 4; a++) {
            float4 v = make_float4(s[a][0] * ATTN_SCALE, s[a][1] * ATTN_SCALE,
                                   s[a][2] * ATTN_SCALE, s[a][3] * ATTN_SCALE);
            *reinterpret_cast<float4*>(&Ps[ty * 4 + a][tx * 4]) = v;
        }
        __syncthreads();

        // Online softmax, one thread per row
        if (tid < 64) {
            float m_old = row_m[tid];
            float mt = m_old;
#pragma unroll 8
            for (int j = 0; j < 64; j++) mt = fmaxf(mt, Ps[tid][j]);
            float alpha = __expf(m_old - mt);
            float lsum = 0.0f;
#pragma unroll 8
            for (int j = 0; j < 64; j++) {
                float p = __expf(Ps[tid][j] - mt);
                Ps[tid][j] = p;
                lsum += p;
            }
            row_m[tid] = mt;
            row_l[tid] = row_l[tid] * alpha + lsum;
            row_alpha[tid] = alpha;
        }
        __syncthreads();

        // O = O*alpha + P @ V
        float al[4];
#pragma unroll
        for (int a = 0; a < 4; a++) al[a] = row_alpha[ty * 4 + a];
#pragma unroll
        for (int a = 0; a < 4; a++)
#pragma unroll
            for (int bb = 0; bb < 4; bb++) o[a][bb] *= al[a];

#pragma unroll
        for (int k = 0; k < 64; k++) {
            float rp[4];
#pragma unroll
            for (int a = 0; a < 4; a++) rp[a] = Ps[ty * 4 + a][k];
            float4 rv = *reinterpret_cast<const float4*>(&Vs[k][tx * 4]);
            float v4[4] = {rv.x, rv.y, rv.z, rv.w};
#pragma unroll
            for (int a = 0; a < 4; a++)
#pragma unroll
                for (int bb = 0; bb < 4; bb++)
                    o[a][bb] = fmaf(rp[a], v4[bb], o[a][bb]);
        }
        __syncthreads();   // protect Ks/Vs/Ps before next tile load
    }

    // Normalize and write ctx[b, q0+row, h*64 + col]
#pragma unroll
    for (int a = 0; a < 4; a++) {
        const int row = ty * 4 + a;
        float inv = 1.0f / row_l[row];
        float4 v = make_float4(o[a][0] * inv, o[a][1] * inv, o[a][2] * inv, o[a][3] * inv);
        *reinterpret_cast<float4*>(
            &ctx[(size_t)(b * LL + q0 + row) * DD + h * DKK + tx * 4]) = v;
    }
}

// ---------------------------------------------------------------------------
extern "C" void kernel_launch(void* const* d_in, const int* in_sizes, int n_in,
                              void* d_out, int out_size)
{
    const float* x     = (const float*)d_in[0];   // [B, L, D]
    const float* w_qkv = (const float*)d_in[1];   // [3D, D]
    const float* w_o   = (const float*)d_in[2];   // [D, D]
    float* out = (float*)d_out;                   // [B, L, D]

    float* qkv_p = nullptr;
    float* ctx_p = nullptr;
    cudaGetSymbolAddress((void**)&qkv_p, g_qkv);
    cudaGetSymbolAddress((void**)&ctx_p, g_ctx);
    cudaFuncSetAttribute(attn_kernel, cudaFuncAttributeMaxDynamicSharedMemorySize, ASM_BYTES);

    // 1) qkv = x @ w_qkv^T   : [8192, 1536]
    {
        dim3 grid(QKVN / 64, MROWS / 64);
        gemm_nt_kernel<<<grid, 256>>>(x, w_qkv, qkv_p, MROWS, QKVN, DD);
    }
    // 2) attention -> ctx
    {
        dim3 grid(LL / 64, BB * HH);
        attn_kernel<<<grid, 256, ASM_BYTES>>>(qkv_p, ctx_p);
    }
    // 3) out = ctx @ w_o^T   : [8192, 512]
    {
        dim3 grid(DD / 64, MROWS / 64);
        gemm_nt_kernel<<<grid, 256>>>(ctx_p, w_o, out, MROWS, DD, DD);
    }
}

// round 2
// speedup vs baseline: 3.0571x; 3.0571x over previous
#include <cuda_runtime.h>
#include <math.h>
#include <stdint.h>

#define BB 2
#define LL 4096
#define DD 512
#define HH 8
#define DKK 64
#define MROWS (BB*LL)          // 8192
#define QKVN (3*DD)            // 1536
#define ATTN_SCALE 0.125f      // 1/sqrt(64)

// Scratch (allocation-free rule: __device__ globals)
__device__ float g_qkv[(size_t)MROWS * QKVN];   // [B*L, 3*D]
__device__ float g_ctx[(size_t)MROWS * DD];     // [B*L, D]

// ---------------------------------------------------------------------------
// Helpers: tf32 convert + m16n8k8 tf32 MMA
// ---------------------------------------------------------------------------
__device__ __forceinline__ uint32_t f2tf(float x) {
    uint32_t u;
    asm("cvt.rna.tf32.f32 %0, %1;" : "=r"(u) : "f"(x));
    return u;
}

__device__ __forceinline__ void mma_tf32(float c[4],
    uint32_t a0, uint32_t a1, uint32_t a2, uint32_t a3,
    uint32_t b0, uint32_t b1)
{
    asm volatile(
        "mma.sync.aligned.m16n8k8.row.col.f32.tf32.tf32.f32 "
        "{%0,%1,%2,%3}, {%4,%5,%6,%7}, {%8,%9}, {%0,%1,%2,%3};"
        : "+f"(c[0]), "+f"(c[1]), "+f"(c[2]), "+f"(c[3])
        : "r"(a0), "r"(a1), "r"(a2), "r"(a3), "r"(b0), "r"(b1));
}

// ---------------------------------------------------------------------------
// fp32 GEMM: C[M,N] = A[M,K] @ W[N,K]^T   (row-major)
// 128x128 tiles, BK=16, 256 threads, 8x8 per-thread micro-tile.
// ---------------------------------------------------------------------------
#define GP 132   // padded tile row length

__global__ __launch_bounds__(256) void gemm_nt_kernel(
    const float* __restrict__ A, const float* __restrict__ W,
    float* __restrict__ C, int M, int N, int K)
{
    __shared__ float As[16][GP];   // [k][m]
    __shared__ float Bs[16][GP];   // [k][n]

    const int tid = threadIdx.x;
    const int tx = tid & 15;        // 0..15 -> n micro
    const int ty = tid >> 4;        // 0..15 -> m micro
    const int m0 = blockIdx.y * 128;
    const int n0 = blockIdx.x * 128;

    const int lr = tid >> 1;            // 0..127 : tile row loaded
    const int lk = (tid & 1) * 8;       // 0 or 8 : k offset

    float acc[8][8] = {};

    for (int k0 = 0; k0 < K; k0 += 16) {
        {
            const float* arow = &A[(size_t)(m0 + lr) * K + k0 + lk];
            const float* brow = &W[(size_t)(n0 + lr) * K + k0 + lk];
            float4 a0 = *reinterpret_cast<const float4*>(arow);
            float4 a1 = *reinterpret_cast<const float4*>(arow + 4);
            float4 b0 = *reinterpret_cast<const float4*>(brow);
            float4 b1 = *reinterpret_cast<const float4*>(brow + 4);
            As[lk + 0][lr] = a0.x; As[lk + 1][lr] = a0.y; As[lk + 2][lr] = a0.z; As[lk + 3][lr] = a0.w;
            As[lk + 4][lr] = a1.x; As[lk + 5][lr] = a1.y; As[lk + 6][lr] = a1.z; As[lk + 7][lr] = a1.w;
            Bs[lk + 0][lr] = b0.x; Bs[lk + 1][lr] = b0.y; Bs[lk + 2][lr] = b0.z; Bs[lk + 3][lr] = b0.w;
            Bs[lk + 4][lr] = b1.x; Bs[lk + 5][lr] = b1.y; Bs[lk + 6][lr] = b1.z; Bs[lk + 7][lr] = b1.w;
        }
        __syncthreads();

#pragma unroll
        for (int k = 0; k < 16; k++) {
            float4 ra0 = *reinterpret_cast<const float4*>(&As[k][ty * 8]);
            float4 ra1 = *reinterpret_cast<const float4*>(&As[k][ty * 8 + 4]);
            float4 rb0 = *reinterpret_cast<const float4*>(&Bs[k][tx * 8]);
            float4 rb1 = *reinterpret_cast<const float4*>(&Bs[k][tx * 8 + 4]);
            float am[8] = {ra0.x, ra0.y, ra0.z, ra0.w, ra1.x, ra1.y, ra1.z, ra1.w};
            float bn[8] = {rb0.x, rb0.y, rb0.z, rb0.w, rb1.x, rb1.y, rb1.z, rb1.w};
#pragma unroll
            for (int a = 0; a < 8; a++)
#pragma unroll
                for (int b = 0; b < 8; b++)
                    acc[a][b] = fmaf(am[a], bn[b], acc[a][b]);
        }
        __syncthreads();
    }

#pragma unroll
    for (int a = 0; a < 8; a++) {
        float* crow = &C[(size_t)(m0 + ty * 8 + a) * N + n0 + tx * 8];
        *reinterpret_cast<float4*>(crow)     = make_float4(acc[a][0], acc[a][1], acc[a][2], acc[a][3]);
        *reinterpret_cast<float4*>(crow + 4) = make_float4(acc[a][4], acc[a][5], acc[a][6], acc[a][7]);
    }
}

// ---------------------------------------------------------------------------
// Flash attention with tf32 tensor-core MMA.
// Block: 256 threads = 8 warps. Br=128 (16 rows/warp), Bc=64, DK=64.
// Q/K/V/P staged in smem as tf32 bit patterns; softmax in registers.
// ---------------------------------------------------------------------------
#define BR 128
#define BC 64
#define KP 68   // pad: conflict-free for row*KP + col fragment patterns
#define VP 72   // pad: conflict-free for k*VP + n fragment patterns

#define SM_QS 0
#define SM_KS (BR*KP)
#define SM_VS (SM_KS + BC*KP)
#define SM_PS (SM_VS + BC*VP)
#define ASM_WORDS (SM_PS + BR*KP)
#define ASM_BYTES (ASM_WORDS * 4)

__global__ __launch_bounds__(256) void attn_tf32_kernel(
    const float* __restrict__ qkv, float* __restrict__ ctx)
{
    extern __shared__ uint32_t sm[];
    uint32_t* Qs = sm + SM_QS;   // [BR][KP]
    uint32_t* Ks = sm + SM_KS;   // [BC][KP]  (token-major: [token][d])
    uint32_t* Vs = sm + SM_VS;   // [BC][VP]  (token-major: [token][d])
    uint32_t* Ps = sm + SM_PS;   // [BR][KP]  (query-major: [q][token])

    const int tid  = threadIdx.x;
    const int warp = tid >> 5;
    const int lane = tid & 31;
    const int g    = lane >> 2;   // 0..7 group (row within half-tile)
    const int tc   = lane & 3;    // 0..3 thread-in-group
    const int wm   = warp * 16;   // warp's first query row in tile

    const int bh = blockIdx.y;
    const int b  = bh >> 3;
    const int h  = bh & 7;
    const int q0 = blockIdx.x * BR;

    const float* base = qkv + (size_t)b * LL * QKVN + h * DKK;

    // Load Q tile (128x64), fold in ATTN_SCALE, convert to tf32.
    {
        const int r  = tid >> 1;
        const int c0 = (tid & 1) * 32;
        const float* qrow = base + (size_t)(q0 + r) * QKVN;
#pragma unroll
        for (int j = 0; j < 32; j += 4) {
            float4 v = *reinterpret_cast<const float4*>(qrow + c0 + j);
            Qs[r * KP + c0 + j + 0] = f2tf(v.x * ATTN_SCALE);
            Qs[r * KP + c0 + j + 1] = f2tf(v.y * ATTN_SCALE);
            Qs[r * KP + c0 + j + 2] = f2tf(v.z * ATTN_SCALE);
            Qs[r * KP + c0 + j + 3] = f2tf(v.w * ATTN_SCALE);
        }
    }

    float oa[8][4];
#pragma unroll
    for (int n = 0; n < 8; n++)
#pragma unroll
        for (int i = 0; i < 4; i++) oa[n][i] = 0.0f;
    float m0 = -1e30f, m1 = -1e30f;    // running max for rows r0=wm+g, r1=wm+g+8
    float l0 = 0.0f,  l1 = 0.0f;       // per-lane partial sums

    for (int kt = 0; kt < LL; kt += BC) {
        __syncthreads();   // previous PV done; safe to overwrite Ks/Vs

        // Load K and V tiles (64x64 each), convert to tf32.
        {
            const int r  = tid >> 2;
            const int c0 = (tid & 3) * 16;
            const float* krow = base + (size_t)(kt + r) * QKVN + DD;
            const float* vrow = krow + DD;
#pragma unroll
            for (int j = 0; j < 16; j += 4) {
                float4 vk = *reinterpret_cast<const float4*>(krow + c0 + j);
                Ks[r * KP + c0 + j + 0] = f2tf(vk.x);
                Ks[r * KP + c0 + j + 1] = f2tf(vk.y);
                Ks[r * KP + c0 + j + 2] = f2tf(vk.z);
                Ks[r * KP + c0 + j + 3] = f2tf(vk.w);
                float4 vv = *reinterpret_cast<const float4*>(vrow + c0 + j);
                Vs[r * VP + c0 + j + 0] = f2tf(vv.x);
                Vs[r * VP + c0 + j + 1] = f2tf(vv.y);
                Vs[r * VP + c0 + j + 2] = f2tf(vv.z);
                Vs[r * VP + c0 + j + 3] = f2tf(vv.w);
            }
        }
        __syncthreads();

        // S = Q @ K^T  : warp computes 16x64 via 8 n-tiles x 8 k-steps
        float sa[8][4];
#pragma unroll
        for (int n = 0; n < 8; n++)
#pragma unroll
            for (int i = 0; i < 4; i++) sa[n][i] = 0.0f;

#pragma unroll
        for (int k = 0; k < 64; k += 8) {
            uint32_t a0 = Qs[(wm + g) * KP + k + tc];
            uint32_t a1 = Qs[(wm + g + 8) * KP + k + tc];
            uint32_t a2 = Qs[(wm + g) * KP + k + tc + 4];
            uint32_t a3 = Qs[(wm + g + 8) * KP + k + tc + 4];
#pragma unroll
            for (int n = 0; n < 8; n++) {
                uint32_t b0 = Ks[(n * 8 + g) * KP + k + tc];
                uint32_t b1 = Ks[(n * 8 + g) * KP + k + tc + 4];
                mma_tf32(sa[n], a0, a1, a2, a3, b0, b1);
            }
        }

        // Online softmax on register fragments.
        float mx0 = -1e30f, mx1 = -1e30f;
#pragma unroll
        for (int n = 0; n < 8; n++) {
            mx0 = fmaxf(mx0, fmaxf(sa[n][0], sa[n][1]));
            mx1 = fmaxf(mx1, fmaxf(sa[n][2], sa[n][3]));
        }
        mx0 = fmaxf(mx0, __shfl_xor_sync(0xffffffffu, mx0, 1));
        mx0 = fmaxf(mx0, __shfl_xor_sync(0xffffffffu, mx0, 2));
        mx1 = fmaxf(mx1, __shfl_xor_sync(0xffffffffu, mx1, 1));
        mx1 = fmaxf(mx1, __shfl_xor_sync(0xffffffffu, mx1, 2));

        float mn0 = fmaxf(m0, mx0);
        float mn1 = fmaxf(m1, mx1);
        float alpha0 = __expf(m0 - mn0);
        float alpha1 = __expf(m1 - mn1);
        m0 = mn0; m1 = mn1;

        float sum0 = 0.0f, sum1 = 0.0f;
#pragma unroll
        for (int n = 0; n < 8; n++) {
            float p0 = __expf(sa[n][0] - m0);
            float p1 = __expf(sa[n][1] - m0);
            float p2 = __expf(sa[n][2] - m1);
            float p3 = __expf(sa[n][3] - m1);
            sum0 += p0 + p1;
            sum1 += p2 + p3;
            sa[n][0] = p0; sa[n][1] = p1; sa[n][2] = p2; sa[n][3] = p3;
        }
        l0 = l0 * alpha0 + sum0;
        l1 = l1 * alpha1 + sum1;

        // Rescale O accumulators.
#pragma unroll
        for (int n = 0; n < 8; n++) {
            oa[n][0] *= alpha0; oa[n][1] *= alpha0;
            oa[n][2] *= alpha1; oa[n][3] *= alpha1;
        }

        // Write P (tf32) to smem.
#pragma unroll
        for (int n = 0; n < 8; n++) {
            Ps[(wm + g) * KP + n * 8 + 2 * tc]     = f2tf(sa[n][0]);
            Ps[(wm + g) * KP + n * 8 + 2 * tc + 1] = f2tf(sa[n][1]);
            Ps[(wm + g + 8) * KP + n * 8 + 2 * tc]     = f2tf(sa[n][2]);
            Ps[(wm + g + 8) * KP + n * 8 + 2 * tc + 1] = f2tf(sa[n][3]);
        }
        __syncthreads();

        // O += P @ V  : 8 k-steps x 8 n-tiles
#pragma unroll
        for (int k = 0; k < 64; k += 8) {
            uint32_t a0 = Ps[(wm + g) * KP + k + tc];
            uint32_t a1 = Ps[(wm + g + 8) * KP + k + tc];
            uint32_t a2 = Ps[(wm + g) * KP + k + tc + 4];
            uint32_t a3 = Ps[(wm + g + 8) * KP + k + tc + 4];
#pragma unroll
            for (int n = 0; n < 8; n++) {
                uint32_t b0 = Vs[(k + tc) * VP + n * 8 + g];
                uint32_t b1 = Vs[(k + tc + 4) * VP + n * 8 + g];
                mma_tf32(oa[n], a0, a1, a2, a3, b0, b1);
            }
        }
    }

    // Finalize l across the quad, normalize, write ctx.
    l0 += __shfl_xor_sync(0xffffffffu, l0, 1);
    l0 += __shfl_xor_sync(0xffffffffu, l0, 2);
    l1 += __shfl_xor_sync(0xffffffffu, l1, 1);
    l1 += __shfl_xor_sync(0xffffffffu, l1, 2);
    float inv0 = 1.0f / l0;
    float inv1 = 1.0f / l1;

    const int r0 = q0 + wm + g;
    const int r1 = r0 + 8;
#pragma unroll
    for (int n = 0; n < 8; n++) {
        float2 v0 = make_float2(oa[n][0] * inv0, oa[n][1] * inv0);
        float2 v1 = make_float2(oa[n][2] * inv1, oa[n][3] * inv1);
        *reinterpret_cast<float2*>(
            &ctx[(size_t)(b * LL + r0) * DD + h * DKK + n * 8 + 2 * tc]) = v0;
        *reinterpret_cast<float2*>(
            &ctx[(size_t)(b * LL + r1) * DD + h * DKK + n * 8 + 2 * tc]) = v1;
    }
}

// ---------------------------------------------------------------------------
extern "C" void kernel_launch(void* const* d_in, const int* in_sizes, int n_in,
                              void* d_out, int out_size)
{
    const float* x     = (const float*)d_in[0];   // [B, L, D]
    const float* w_qkv = (const float*)d_in[1];   // [3D, D]
    const float* w_o   = (const float*)d_in[2];   // [D, D]
    float* out = (float*)d_out;                   // [B, L, D]

    float* qkv_p = nullptr;
    float* ctx_p = nullptr;
    cudaGetSymbolAddress((void**)&qkv_p, g_qkv);
    cudaGetSymbolAddress((void**)&ctx_p, g_ctx);
    cudaFuncSetAttribute(attn_tf32_kernel, cudaFuncAttributeMaxDynamicSharedMemorySize, ASM_BYTES);

    // 1) qkv = x @ w_qkv^T   : [8192, 1536]
    {
        dim3 grid(QKVN / 128, MROWS / 128);
        gemm_nt_kernel<<<grid, 256>>>(x, w_qkv, qkv_p, MROWS, QKVN, DD);
    }
    // 2) attention -> ctx
    {
        dim3 grid(LL / BR, BB * HH);
        attn_tf32_kernel<<<grid, 256, ASM_BYTES>>>(qkv_p, ctx_p);
    }
    // 3) out = ctx @ w_o^T   : [8192, 512]
    {
        dim3 grid(DD / 128, MROWS / 128);
        gemm_nt_kernel<<<grid, 256>>>(ctx_p, w_o, out, MROWS, DD, DD);
    }
}

// round 3
// speedup vs baseline: 4.3124x; 1.4106x over previous
#include <cuda_runtime.h>
#include <math.h>
#include <stdint.h>

#define BB 2
#define LL 4096
#define DD 512
#define HH 8
#define DKK 64
#define MROWS (BB*LL)          // 8192
#define QKVN (3*DD)            // 1536
#define ATTN_SCALE 0.125f      // 1/sqrt(64)

// Scratch (allocation-free rule: __device__ globals)
__device__ float g_qkv[(size_t)MROWS * QKVN];   // [B*L, 3*D]
__device__ float g_ctx[(size_t)MROWS * DD];     // [B*L, D]

// ---------------------------------------------------------------------------
// Helpers: tf32 convert + m16n8k8 tf32 MMA
// ---------------------------------------------------------------------------
__device__ __forceinline__ uint32_t f2tf(float x) {
    uint32_t u;
    asm("cvt.rna.tf32.f32 %0, %1;" : "=r"(u) : "f"(x));
    return u;
}

__device__ __forceinline__ void mma_tf32(float c[4],
    uint32_t a0, uint32_t a1, uint32_t a2, uint32_t a3,
    uint32_t b0, uint32_t b1)
{
    asm volatile(
        "mma.sync.aligned.m16n8k8.row.col.f32.tf32.tf32.f32 "
        "{%0,%1,%2,%3}, {%4,%5,%6,%7}, {%8,%9}, {%0,%1,%2,%3};"
        : "+f"(c[0]), "+f"(c[1]), "+f"(c[2]), "+f"(c[3])
        : "r"(a0), "r"(a1), "r"(a2), "r"(a3), "r"(b0), "r"(b1));
}

// ---------------------------------------------------------------------------
// tf32 GEMM: C[M,N] = A[M,K] @ W[N,K]^T  (row-major)
// Block tile 128x128, BK=32, 256 threads = 8 warps (4m x 2n),
// warp tile 32x64 (2 m16-frags x 8 n8-frags).
// ---------------------------------------------------------------------------
#define GPAD 36   // 32 k + 4 pad; (row*36 + k + tc) is bank-conflict-free

__global__ __launch_bounds__(256, 2) void gemm_tf32_kernel(
    const float* __restrict__ A, const float* __restrict__ W,
    float* __restrict__ C, int M, int N, int K)
{
    __shared__ uint32_t As[128 * GPAD];   // [m][k] tf32
    __shared__ uint32_t Ws[128 * GPAD];   // [n][k] tf32

    const int tid  = threadIdx.x;
    const int warp = tid >> 5;
    const int lane = tid & 31;
    const int g    = lane >> 2;
    const int tc   = lane & 3;
    const int wm   = (warp >> 1) * 32;    // warp m base within tile
    const int wn   = (warp & 1) * 64;     // warp n base within tile
    const int m0   = blockIdx.y * 128;
    const int n0   = blockIdx.x * 128;

    const int lrow = tid >> 1;            // 0..127 : tile row this thread loads
    const int lkof = (tid & 1) * 16;      // 0 / 16

    float acc[2][8][4];
#pragma unroll
    for (int mf = 0; mf < 2; mf++)
#pragma unroll
        for (int nf = 0; nf < 8; nf++)
#pragma unroll
            for (int i = 0; i < 4; i++) acc[mf][nf][i] = 0.0f;

    for (int k0 = 0; k0 < K; k0 += 32) {
        {
            const float* arow = &A[(size_t)(m0 + lrow) * K + k0 + lkof];
            const float* wrow = &W[(size_t)(n0 + lrow) * K + k0 + lkof];
#pragma unroll
            for (int j = 0; j < 16; j += 4) {
                float4 va = *reinterpret_cast<const float4*>(arow + j);
                As[lrow * GPAD + lkof + j + 0] = f2tf(va.x);
                As[lrow * GPAD + lkof + j + 1] = f2tf(va.y);
                As[lrow * GPAD + lkof + j + 2] = f2tf(va.z);
                As[lrow * GPAD + lkof + j + 3] = f2tf(va.w);
                float4 vw = *reinterpret_cast<const float4*>(wrow + j);
                Ws[lrow * GPAD + lkof + j + 0] = f2tf(vw.x);
                Ws[lrow * GPAD + lkof + j + 1] = f2tf(vw.y);
                Ws[lrow * GPAD + lkof + j + 2] = f2tf(vw.z);
                Ws[lrow * GPAD + lkof + j + 3] = f2tf(vw.w);
            }
        }
        __syncthreads();

#pragma unroll
        for (int kk = 0; kk < 4; kk++) {
            const int kb = kk * 8;
            uint32_t a[2][4];
#pragma unroll
            for (int mf = 0; mf < 2; mf++) {
                const int rb = wm + mf * 16;
                a[mf][0] = As[(rb + g) * GPAD + kb + tc];
                a[mf][1] = As[(rb + g + 8) * GPAD + kb + tc];
                a[mf][2] = As[(rb + g) * GPAD + kb + tc + 4];
                a[mf][3] = As[(rb + g + 8) * GPAD + kb + tc + 4];
            }
#pragma unroll
            for (int nf = 0; nf < 8; nf++) {
                uint32_t b0 = Ws[(wn + nf * 8 + g) * GPAD + kb + tc];
                uint32_t b1 = Ws[(wn + nf * 8 + g) * GPAD + kb + tc + 4];
                mma_tf32(acc[0][nf], a[0][0], a[0][1], a[0][2], a[0][3], b0, b1);
                mma_tf32(acc[1][nf], a[1][0], a[1][1], a[1][2], a[1][3], b0, b1);
            }
        }
        __syncthreads();
    }

#pragma unroll
    for (int mf = 0; mf < 2; mf++) {
        const int r0 = m0 + wm + mf * 16 + g;
#pragma unroll
        for (int nf = 0; nf < 8; nf++) {
            const int cc = n0 + wn + nf * 8 + 2 * tc;
            *reinterpret_cast<float2*>(&C[(size_t)r0 * N + cc]) =
                make_float2(acc[mf][nf][0], acc[mf][nf][1]);
            *reinterpret_cast<float2*>(&C[(size_t)(r0 + 8) * N + cc]) =
                make_float2(acc[mf][nf][2], acc[mf][nf][3]);
        }
    }
}

// ---------------------------------------------------------------------------
// Flash attention with tf32 MMA. Block: 256 threads = 8 warps.
// Br=128 (16 rows/warp), Bc=64, DK=64. P never touches smem: the S-accumulator
// fragments are permuted into PV A-fragments with warp shuffles.
// ---------------------------------------------------------------------------
#define BR 128
#define BC 64
#define KP 68   // pad for [row][d] tiles
#define VP 72   // pad for [token][d] V tile read pattern

#define SM_QS 0
#define SM_KS (BR*KP)
#define SM_VS (SM_KS + BC*KP)
#define ASM_WORDS (SM_VS + BC*VP)
#define ASM_BYTES (ASM_WORDS * 4)

__global__ __launch_bounds__(256, 2) void attn_tf32_kernel(
    const float* __restrict__ qkv, float* __restrict__ ctx)
{
    extern __shared__ uint32_t sm[];
    uint32_t* Qs = sm + SM_QS;   // [BR][KP]
    uint32_t* Ks = sm + SM_KS;   // [BC][KP]
    uint32_t* Vs = sm + SM_VS;   // [BC][VP]

    const int tid  = threadIdx.x;
    const int warp = tid >> 5;
    const int lane = tid & 31;
    const int g    = lane >> 2;
    const int tc   = lane & 3;
    const int wm   = warp * 16;

    const int bh = blockIdx.y;
    const int b  = bh >> 3;
    const int h  = bh & 7;
    const int q0 = blockIdx.x * BR;

    const float* base = qkv + (size_t)b * LL * QKVN + h * DKK;

    // Load Q tile (128x64), fold in ATTN_SCALE, convert to tf32.
    {
        const int r  = tid >> 1;
        const int c0 = (tid & 1) * 32;
        const float* qrow = base + (size_t)(q0 + r) * QKVN;
#pragma unroll
        for (int j = 0; j < 32; j += 4) {
            float4 v = *reinterpret_cast<const float4*>(qrow + c0 + j);
            Qs[r * KP + c0 + j + 0] = f2tf(v.x * ATTN_SCALE);
            Qs[r * KP + c0 + j + 1] = f2tf(v.y * ATTN_SCALE);
            Qs[r * KP + c0 + j + 2] = f2tf(v.z * ATTN_SCALE);
            Qs[r * KP + c0 + j + 3] = f2tf(v.w * ATTN_SCALE);
        }
    }

    float oa[8][4];
#pragma unroll
    for (int n = 0; n < 8; n++)
#pragma unroll
        for (int i = 0; i < 4; i++) oa[n][i] = 0.0f;
    float m0 = -1e30f, m1 = -1e30f;
    float l0 = 0.0f,  l1 = 0.0f;

    // shuffle source lanes for the P fragment permutation
    const int srcA = g * 4 + (tc >> 1);       // cols tc      (parity tc&1)
    const int srcB = srcA + 2;                // cols tc+4

    for (int kt = 0; kt < LL; kt += BC) {
        __syncthreads();   // prior PV done; safe to overwrite Ks/Vs

        // Load K and V tiles (64x64 each), convert to tf32.
        {
            const int r  = tid >> 2;
            const int c0 = (tid & 3) * 16;
            const float* krow = base + (size_t)(kt + r) * QKVN + DD;
            const float* vrow = krow + DD;
#pragma unroll
            for (int j = 0; j < 16; j += 4) {
                float4 vk = *reinterpret_cast<const float4*>(krow + c0 + j);
                Ks[r * KP + c0 + j + 0] = f2tf(vk.x);
                Ks[r * KP + c0 + j + 1] = f2tf(vk.y);
                Ks[r * KP + c0 + j + 2] = f2tf(vk.z);
                Ks[r * KP + c0 + j + 3] = f2tf(vk.w);
                float4 vv = *reinterpret_cast<const float4*>(vrow + c0 + j);
                Vs[r * VP + c0 + j + 0] = f2tf(vv.x);
                Vs[r * VP + c0 + j + 1] = f2tf(vv.y);
                Vs[r * VP + c0 + j + 2] = f2tf(vv.z);
                Vs[r * VP + c0 + j + 3] = f2tf(vv.w);
            }
        }
        __syncthreads();

        // S = Q @ K^T : 16x64 per warp
        float sa[8][4];
#pragma unroll
        for (int n = 0; n < 8; n++)
#pragma unroll
            for (int i = 0; i < 4; i++) sa[n][i] = 0.0f;

#pragma unroll
        for (int k = 0; k < 64; k += 8) {
            uint32_t a0 = Qs[(wm + g) * KP + k + tc];
            uint32_t a1 = Qs[(wm + g + 8) * KP + k + tc];
            uint32_t a2 = Qs[(wm + g) * KP + k + tc + 4];
            uint32_t a3 = Qs[(wm + g + 8) * KP + k + tc + 4];
#pragma unroll
            for (int n = 0; n < 8; n++) {
                uint32_t b0 = Ks[(n * 8 + g) * KP + k + tc];
                uint32_t b1 = Ks[(n * 8 + g) * KP + k + tc + 4];
                mma_tf32(sa[n], a0, a1, a2, a3, b0, b1);
            }
        }

        // Online softmax on fragments.
        float mx0 = -1e30f, mx1 = -1e30f;
#pragma unroll
        for (int n = 0; n < 8; n++) {
            mx0 = fmaxf(mx0, fmaxf(sa[n][0], sa[n][1]));
            mx1 = fmaxf(mx1, fmaxf(sa[n][2], sa[n][3]));
        }
        mx0 = fmaxf(mx0, __shfl_xor_sync(0xffffffffu, mx0, 1));
        mx0 = fmaxf(mx0, __shfl_xor_sync(0xffffffffu, mx0, 2));
        mx1 = fmaxf(mx1, __shfl_xor_sync(0xffffffffu, mx1, 1));
        mx1 = fmaxf(mx1, __shfl_xor_sync(0xffffffffu, mx1, 2));

        float mn0 = fmaxf(m0, mx0);
        float mn1 = fmaxf(m1, mx1);
        float alpha0 = __expf(m0 - mn0);
        float alpha1 = __expf(m1 - mn1);
        m0 = mn0; m1 = mn1;

        float sum0 = 0.0f, sum1 = 0.0f;
#pragma unroll
        for (int n = 0; n < 8; n++) {
            float p0 = __expf(sa[n][0] - m0);
            float p1 = __expf(sa[n][1] - m0);
            float p2 = __expf(sa[n][2] - m1);
            float p3 = __expf(sa[n][3] - m1);
            sum0 += p0 + p1;
            sum1 += p2 + p3;
            sa[n][0] = p0; sa[n][1] = p1; sa[n][2] = p2; sa[n][3] = p3;
        }
        l0 = l0 * alpha0 + sum0;
        l1 = l1 * alpha1 + sum1;

#pragma unroll
        for (int n = 0; n < 8; n++) {
            oa[n][0] *= alpha0; oa[n][1] *= alpha0;
            oa[n][2] *= alpha1; oa[n][3] *= alpha1;
        }

        // O += P @ V. P A-fragments come from S C-fragments via shuffles:
        // P[r][kk*8 + j] lives in sa[kk][c] of lane g*4 + (j>>1), c by parity.
        const bool odd = (tc & 1);
#pragma unroll
        for (int kk = 0; kk < 8; kk++) {
            float v00 = __shfl_sync(0xffffffffu, sa[kk][0], srcA);
            float v01 = __shfl_sync(0xffffffffu, sa[kk][1], srcA);
            float v10 = __shfl_sync(0xffffffffu, sa[kk][2], srcA);
            float v11 = __shfl_sync(0xffffffffu, sa[kk][3], srcA);
            float w00 = __shfl_sync(0xffffffffu, sa[kk][0], srcB);
            float w01 = __shfl_sync(0xffffffffu, sa[kk][1], srcB);
            float w10 = __shfl_sync(0xffffffffu, sa[kk][2], srcB);
            float w11 = __shfl_sync(0xffffffffu, sa[kk][3], srcB);
            uint32_t pa0 = f2tf(odd ? v01 : v00);
            uint32_t pa1 = f2tf(odd ? v11 : v10);
            uint32_t pa2 = f2tf(odd ? w01 : w00);
            uint32_t pa3 = f2tf(odd ? w11 : w10);
            const int kb = kk * 8;
#pragma unroll
            for (int n = 0; n < 8; n++) {
                uint32_t b0 = Vs[(kb + tc) * VP + n * 8 + g];
                uint32_t b1 = Vs[(kb + tc + 4) * VP + n * 8 + g];
                mma_tf32(oa[n], pa0, pa1, pa2, pa3, b0, b1);
            }
        }
    }

    // Finalize l across the quad, normalize, write ctx.
    l0 += __shfl_xor_sync(0xffffffffu, l0, 1);
    l0 += __shfl_xor_sync(0xffffffffu, l0, 2);
    l1 += __shfl_xor_sync(0xffffffffu, l1, 1);
    l1 += __shfl_xor_sync(0xffffffffu, l1, 2);
    float inv0 = 1.0f / l0;
    float inv1 = 1.0f / l1;

    const int r0 = q0 + wm + g;
    const int r1 = r0 + 8;
#pragma unroll
    for (int n = 0; n < 8; n++) {
        *reinterpret_cast<float2*>(
            &ctx[(size_t)(b * LL + r0) * DD + h * DKK + n * 8 + 2 * tc]) =
            make_float2(oa[n][0] * inv0, oa[n][1] * inv0);
        *reinterpret_cast<float2*>(
            &ctx[(size_t)(b * LL + r1) * DD + h * DKK + n * 8 + 2 * tc]) =
            make_float2(oa[n][2] * inv1, oa[n][3] * inv1);
    }
}

// ---------------------------------------------------------------------------
extern "C" void kernel_launch(void* const* d_in, const int* in_sizes, int n_in,
                              void* d_out, int out_size)
{
    const float* x     = (const float*)d_in[0];   // [B, L, D]
    const float* w_qkv = (const float*)d_in[1];   // [3D, D]
    const float* w_o   = (const float*)d_in[2];   // [D, D]
    float* out = (float*)d_out;                   // [B, L, D]

    float* qkv_p = nullptr;
    float* ctx_p = nullptr;
    cudaGetSymbolAddress((void**)&qkv_p, g_qkv);
    cudaGetSymbolAddress((void**)&ctx_p, g_ctx);
    cudaFuncSetAttribute(attn_tf32_kernel, cudaFuncAttributeMaxDynamicSharedMemorySize, ASM_BYTES);

    // 1) qkv = x @ w_qkv^T : [8192, 1536]
    {
        dim3 grid(QKVN / 128, MROWS / 128);
        gemm_tf32_kernel<<<grid, 256>>>(x, w_qkv, qkv_p, MROWS, QKVN, DD);
    }
    // 2) attention -> ctx
    {
        dim3 grid(LL / BR, BB * HH);
        attn_tf32_kernel<<<grid, 256, ASM_BYTES>>>(qkv_p, ctx_p);
    }
    // 3) out = ctx @ w_o^T : [8192, 512]
    {
        dim3 grid(DD / 128, MROWS / 128);
        gemm_tf32_kernel<<<grid, 256>>>(ctx_p, w_o, out, MROWS, DD, DD);
    }
}